// round 5
// baseline (speedup 1.0000x reference)
#include <cuda_runtime.h>

#define N_GAUSS 4096
#define N_PTS 32768
#define NSPLIT 4
#define NBLK 128                 /* gaussian blocks of 32 */
#define U2G 14                   /* ulonglong2 per gaussian (28 dup float2 slots) */
#define NCELL 4096               /* 16^3 grid, cell side 0.5 over [-4,4] */
#define MAXITEMS 4608

typedef unsigned long long u64;

__device__ ulonglong2 g_prm2[N_GAUSS * U2G];
__device__ float4 g_ginfo[N_GAUSS];            // center xyz, T
__device__ float  g_partial[NSPLIT * 2 * N_PTS];
__device__ int    g_cnt[NCELL];
__device__ int    g_off[NCELL];
__device__ int    g_cur[NCELL];
__device__ int    g_cid[N_PTS];
__device__ int    g_perm[N_PTS];
__device__ float4 g_spts[N_PTS];
__device__ unsigned g_mask[NCELL * NBLK];
__device__ int2   g_items[MAXITEMS];
__device__ int    g_nitems;

__device__ __forceinline__ float ex2f(float x) {
    float y; asm("ex2.approx.ftz.f32 %0, %1;" : "=f"(y) : "f"(x)); return y;
}
__device__ __forceinline__ float rsqf(float x) {
    float y; asm("rsqrt.approx.ftz.f32 %0, %1;" : "=f"(y) : "f"(x)); return y;
}
__device__ __forceinline__ u64 f2fma(u64 a, u64 b, u64 c) {
    u64 d; asm("fma.rn.f32x2 %0, %1, %2, %3;" : "=l"(d) : "l"(a), "l"(b), "l"(c)); return d;
}
__device__ __forceinline__ u64 f2mul(u64 a, u64 b) {
    u64 d; asm("mul.rn.f32x2 %0, %1, %2;" : "=l"(d) : "l"(a), "l"(b)); return d;
}
__device__ __forceinline__ u64 f2add(u64 a, u64 b) {
    u64 d; asm("add.rn.f32x2 %0, %1, %2;" : "=l"(d) : "l"(a), "l"(b)); return d;
}
__device__ __forceinline__ u64 f2pack(float lo, float hi) {
    u64 d; asm("mov.b64 %0, {%1, %2};" : "=l"(d) : "f"(lo), "f"(hi)); return d;
}
__device__ __forceinline__ void f2unpack(u64 v, float& lo, float& hi) {
    asm("mov.b64 {%0, %1}, %2;" : "=f"(lo), "=f"(hi) : "l"(v));
}
__device__ __forceinline__ u64 f2relu(u64 v) {
    unsigned lo = (unsigned)v, hi = (unsigned)(v >> 32);
    lo &= ~(unsigned)(((int)lo) >> 31);
    hi &= ~(unsigned)(((int)hi) >> 31);
    return ((u64)hi << 32) | lo;
}

// ---------------------------------------------------------------------------
// Spatial binning of points (cell = 0.5, 16^3 over [-4,4], borders clamped).
// ---------------------------------------------------------------------------
__global__ void zero_kernel() {
    int i = blockIdx.x * blockDim.x + threadIdx.x;
    if (i < NCELL) g_cnt[i] = 0;
}

__global__ void cell_count(const float* __restrict__ pts) {
    int i = blockIdx.x * blockDim.x + threadIdx.x;
    if (i >= N_PTS) return;
    float x = pts[i*3+0], y = pts[i*3+1], z = pts[i*3+2];
    int ix = min(15, max(0, (int)floorf((x + 4.f) * 2.f)));
    int iy = min(15, max(0, (int)floorf((y + 4.f) * 2.f)));
    int iz = min(15, max(0, (int)floorf((z + 4.f) * 2.f)));
    int c = ix | (iy << 4) | (iz << 8);
    g_cid[i] = c;
    atomicAdd(&g_cnt[c], 1);
}

__global__ void __launch_bounds__(1024) scan_kernel() {
    __shared__ int ps[1024];
    int t = threadIdx.x;
    int l0 = g_cnt[t*4+0], l1 = g_cnt[t*4+1], l2 = g_cnt[t*4+2], l3 = g_cnt[t*4+3];
    int s = l0 + l1 + l2 + l3;
    ps[t] = s; __syncthreads();
    for (int off = 1; off < 1024; off <<= 1) {
        int v = (t >= off) ? ps[t - off] : 0;
        __syncthreads();
        ps[t] += v;
        __syncthreads();
    }
    int run = ps[t] - s;
    g_off[t*4+0] = run; g_cur[t*4+0] = run; run += l0;
    g_off[t*4+1] = run; g_cur[t*4+1] = run; run += l1;
    g_off[t*4+2] = run; g_cur[t*4+2] = run; run += l2;
    g_off[t*4+3] = run; g_cur[t*4+3] = run;
}

__global__ void scatter_kernel(const float* __restrict__ pts) {
    int i = blockIdx.x * blockDim.x + threadIdx.x;
    if (i >= N_PTS) return;
    int slot = atomicAdd(&g_cur[g_cid[i]], 1);
    g_perm[slot] = i;
    // store NEGATED coords (main kernel computes e = g + (-p))
    g_spts[slot] = make_float4(-pts[i*3+0], -pts[i*3+1], -pts[i*3+2], 0.f);
}

// ---------------------------------------------------------------------------
// Worklist: one item per <=64 points of one cell. Deterministic (built from
// counts/offsets in cell order). item.x = start | (npts<<16), item.y = cell.
// ---------------------------------------------------------------------------
__global__ void __launch_bounds__(1024) worklist_kernel() {
    __shared__ int ps[1024];
    int t = threadIdx.x;
    int ic[4]; int s = 0;
#pragma unroll
    for (int k = 0; k < 4; ++k) {
        int n = g_cnt[t*4+k];
        ic[k] = (n + 63) >> 6;
        s += ic[k];
    }
    ps[t] = s; __syncthreads();
    for (int off = 1; off < 1024; off <<= 1) {
        int v = (t >= off) ? ps[t - off] : 0;
        __syncthreads();
        ps[t] += v;
        __syncthreads();
    }
    int base = ps[t] - s;
#pragma unroll
    for (int k = 0; k < 4; ++k) {
        int c = t*4 + k;
        int n = g_cnt[c], off = g_off[c];
        for (int w = 0; w < ic[k]; ++w) {
            int st = off + 64*w;
            int np = min(64, n - 64*w);
            g_items[base++] = make_int2(st | (np << 16), c);
        }
    }
    if (t == 1023) g_nitems = ps[1023];
}

// ---------------------------------------------------------------------------
// Per-gaussian preprocessing (same dup layout as R4) + ginfo for mask build.
//  slots: 0:gx 1:gy 2:gz 3:T 4..9:P0..P5 10:op 11:c0 12..27:c1..c15
// ---------------------------------------------------------------------------
__global__ void prep_kernel(const float* __restrict__ xyz,
                            const float* __restrict__ sh_dc,
                            const float* __restrict__ sh_rest,
                            const float* __restrict__ scaling,
                            const float* __restrict__ rotation,
                            const float* __restrict__ opacity) {
    int g = blockIdx.x * blockDim.x + threadIdx.x;
    if (g >= N_GAUSS) return;

    float qr = rotation[g*4+0], qx = rotation[g*4+1];
    float qy = rotation[g*4+2], qz = rotation[g*4+3];
    float qn = rsqrtf(qr*qr + qx*qx + qy*qy + qz*qz);
    qr *= qn; qx *= qn; qy *= qn; qz *= qn;

    float R00 = 1.f - 2.f*(qy*qy + qz*qz), R01 = 2.f*(qx*qy - qr*qz), R02 = 2.f*(qx*qz + qr*qy);
    float R10 = 2.f*(qx*qy + qr*qz), R11 = 1.f - 2.f*(qx*qx + qz*qz), R12 = 2.f*(qy*qz - qr*qx);
    float R20 = 2.f*(qx*qz - qr*qy), R21 = 2.f*(qy*qz + qr*qx), R22 = 1.f - 2.f*(qx*qx + qy*qy);

    float s0 = expf(scaling[g*3+0]);
    float s1 = expf(scaling[g*3+1]);
    float s2 = expf(scaling[g*3+2]);
    float iv0 = 1.f/(s0*s0), iv1 = 1.f/(s1*s1), iv2 = 1.f/(s2*s2);
    float smax = fmaxf(s0, fmaxf(s1, s2));
    float T = 230.f * smax * smax;

    float Pxx = iv0*R00*R00 + iv1*R01*R01 + iv2*R02*R02;
    float Pyy = iv0*R10*R10 + iv1*R11*R11 + iv2*R12*R12;
    float Pzz = iv0*R20*R20 + iv1*R21*R21 + iv2*R22*R22;
    float Pxy = iv0*R00*R10 + iv1*R01*R11 + iv2*R02*R12;
    float Pxz = iv0*R00*R20 + iv1*R01*R21 + iv2*R02*R22;
    float Pyz = iv0*R10*R20 + iv1*R11*R21 + iv2*R12*R22;

    const float kk = -0.7213475204444817f;  // -0.5 * log2(e)
    float op = 1.f / (1.f + expf(-opacity[g]));

    const float C0 = 0.28209479177387814f;
    const float C1 = 0.4886025119029199f;
    const float* sr = sh_rest + g*15;
    float c[16];
    c[0]  =  C0 * sh_dc[g];
    c[1]  = -C1 * sr[0];
    c[2]  =  C1 * sr[1];
    c[3]  = -C1 * sr[2];
    c[4]  =  1.0925484305920792f  * sr[3];
    c[5]  = -1.0925484305920792f  * sr[4];
    c[6]  =  0.31539156525252005f * sr[5];
    c[7]  = -1.0925484305920792f  * sr[6];
    c[8]  =  0.5462742152960396f  * sr[7];
    c[9]  = -0.5900435899266435f  * sr[8];
    c[10] =  2.890611442640554f   * sr[9];
    c[11] = -0.4570457994644658f  * sr[10];
    c[12] =  0.3731763325901154f  * sr[11];
    c[13] = -0.4570457994644658f  * sr[12];
    c[14] =  1.445305721320277f   * sr[13];
    c[15] = -0.5900435899266435f  * sr[14];

    float gx = xyz[g*3+0], gy = xyz[g*3+1], gz = xyz[g*3+2];
    g_ginfo[g] = make_float4(gx, gy, gz, T);

    float v[28];
    v[0] = gx; v[1] = gy; v[2] = gz; v[3] = T;
    v[4] = kk*Pxx; v[5] = kk*Pyy; v[6] = kk*Pzz;
    v[7] = 2.f*kk*Pxy; v[8] = 2.f*kk*Pxz; v[9] = 2.f*kk*Pyz;
    v[10] = op; v[11] = c[0];
#pragma unroll
    for (int i = 0; i < 15; ++i) v[12+i] = c[1+i];
    v[27] = 0.f;

    float2* o = (float2*)&g_prm2[g * U2G];
#pragma unroll
    for (int i = 0; i < 28; ++i) o[i] = make_float2(v[i], v[i]);
}

// ---------------------------------------------------------------------------
// Mask build: one warp per cell. Bit g%32 of g_mask[cell*128 + g/32] set iff
// dist(cell box, gaussian center)^2 < T. Border cells extended to infinity
// (points are clamped into border cells). Deterministic.
// ---------------------------------------------------------------------------
__global__ void __launch_bounds__(256) mask_kernel() {
    int warp = (blockIdx.x * 256 + threadIdx.x) >> 5;
    int lane = threadIdx.x & 31;
    if (warp >= NCELL) return;
    int ix = warp & 15, iy = (warp >> 4) & 15, iz = (warp >> 8) & 15;
    float lox = ix*0.5f - 4.f, hix = lox + 0.5f;
    float loy = iy*0.5f - 4.f, hiy = loy + 0.5f;
    float loz = iz*0.5f - 4.f, hiz = loz + 0.5f;
    if (ix == 0) lox = -1e30f;  if (ix == 15) hix = 1e30f;
    if (iy == 0) loy = -1e30f;  if (iy == 15) hiy = 1e30f;
    if (iz == 0) loz = -1e30f;  if (iz == 15) hiz = 1e30f;

    for (int blk = 0; blk < NBLK; ++blk) {
        float4 gi = g_ginfo[blk*32 + lane];
        float dx = gi.x - fminf(fmaxf(gi.x, lox), hix);
        float dy = gi.y - fminf(fmaxf(gi.y, loy), hiy);
        float dz = gi.z - fminf(fmaxf(gi.z, loz), hiz);
        float d2 = dx*dx + dy*dy + dz*dz;
        unsigned m = __ballot_sync(0xFFFFFFFFu, d2 < gi.w);
        if (lane == 0) g_mask[warp*NBLK + blk] = m;
    }
}

// ---------------------------------------------------------------------------
// Main kernel: CTA = one work item (<=64 points of one cell, 2 pts/lane).
// 4 warps = 4 gaussian-block splits. Each warp walks only the set mask bits,
// with a second-level per-warp ballot cull before the full evaluation.
// ---------------------------------------------------------------------------
__global__ void __launch_bounds__(128) main_kernel() {
    int item = blockIdx.x;
    if (item >= g_nitems) return;
    int split = threadIdx.x >> 5;
    int lane  = threadIdx.x & 31;

    int2 it = g_items[item];
    int start = it.x & 0xFFFF;
    int npts  = it.x >> 16;
    int cell  = it.y;

    bool v0 = (2*lane     < npts);
    bool v1 = (2*lane + 1 < npts);
    int s0 = start + 2*lane;
    int s1 = s0 + 1;
    float4 pa = g_spts[v0 ? s0 : start];
    float4 pb = g_spts[v1 ? s1 : start];
    u64 npx = f2pack(pa.x, pb.x);
    u64 npy = f2pack(pa.y, pb.y);
    u64 npz = f2pack(pa.z, pb.z);

    const u64 K3  = 0x4040000040400000ULL;  // { 3, 3}
    const u64 K5  = 0x40A0000040A00000ULL;  // { 5, 5}
    const u64 Kn2 = 0xC0000000C0000000ULL;  // {-2,-2}
    const u64 Kn3 = 0xC0400000C0400000ULL;  // {-3,-3}
    const u64 SGN = 0x8000000080000000ULL;

    u64 wacc = 0, ssacc = 0;

    for (int blk = split; blk < NBLK; blk += NSPLIT) {
        unsigned m = g_mask[cell*NBLK + blk];
        while (m) {
            int j = __ffs(m) - 1;
            m &= m - 1;
            const ulonglong2* G = &g_prm2[(blk*32 + j) * U2G];
            ulonglong2 q0 = G[0], q1 = G[1];

            u64 ex = f2add(q0.x, npx);   // e = gauss - point
            u64 ey = f2add(q0.y, npy);
            u64 ez = f2add(q1.x, npz);
            u64 exx = f2mul(ex, ex), eyy = f2mul(ey, ey), ezz = f2mul(ez, ez);
            u64 n2 = f2add(f2add(exx, eyy), ezz);

            float nA, nB; f2unpack(n2, nA, nB);
            float Tv, Tv2; f2unpack(q1.y, Tv, Tv2);
            bool act = (nA < Tv) || (nB < Tv);
            if (__ballot_sync(0xFFFFFFFFu, act)) {
                ulonglong2 q2 = G[2], q3 = G[3], q4 = G[4];
                u64 pxy = f2mul(ex, ey), pxz = f2mul(ex, ez), pyz = f2mul(ey, ez);

                // exponent (pre-scaled by -0.5*log2e)
                u64 mm = f2mul(exx, q2.x);
                mm = f2fma(eyy, q2.y, mm);
                mm = f2fma(ezz, q3.x, mm);
                mm = f2fma(pxy, q3.y, mm);
                mm = f2fma(pxz, q4.x, mm);
                mm = f2fma(pyz, q4.y, mm);

                // aux polynomials in e
                u64 n2n  = n2 ^ SGN;
                u64 eyyn = eyy ^ SGN;
                u64 t6  = f2fma(K3, ezz, n2n);    // 3ezz - n2
                u64 uq  = f2add(exx, eyyn);       // exx - eyy
                u64 t9  = f2fma(K3, exx, eyyn);   // 3exx - eyy
                u64 w5  = f2fma(K5, ezz, n2n);    // 5ezz - n2
                u64 t12 = f2fma(Kn2, n2, w5);     // 5ezz - 3n2
                u64 t15 = f2fma(Kn3, ezz, uq);    // exx - eyy - 3ezz

                ulonglong2 q5 = G[5], q6 = G[6], q7 = G[7];
                u64 S1 = f2fma(ex, q7.x, f2fma(ez, q6.y, f2mul(ey, q6.x)));
                ulonglong2 q8 = G[8], q9 = G[9];
                u64 S2 = f2fma(uq, q9.y,
                         f2fma(pxz, q9.x,
                         f2fma(t6, q8.y,
                         f2fma(pyz, q8.x, f2mul(pxy, q7.y)))));
                ulonglong2 q10 = G[10], q11 = G[11], q12 = G[12], q13 = G[13];
                u64 m9  = f2mul(ey, t9);
                u64 m11 = f2mul(ey, w5);
                u64 m13 = f2mul(ex, w5);
                u64 m15 = f2mul(ex, t15);
                u64 S3a = f2mul(m9, q10.x);
                S3a = f2fma(m11, q11.x, S3a);
                S3a = f2fma(m13, q12.x, S3a);
                S3a = f2fma(m15, q13.x, S3a);
                u64 m10 = f2mul(pxy, ez);
                u64 m12 = f2mul(ez, t12);
                u64 m14 = f2mul(ez, uq);
                u64 S3b = f2mul(m10, q10.y);
                S3b = f2fma(m12, q11.y, S3b);
                S3b = f2fma(m14, q12.y, S3b);
                u64 S3 = f2add(S3a, S3b);

                // Horner in rinv: res = c0 + r*(S1 + r*(S2 + r*S3))
                u64 rq = f2pack(rsqf(nA), rsqf(nB));
                u64 res = f2fma(rq, S3, S2);
                res = f2fma(rq, res, S1);
                res = f2fma(rq, res, q5.y);

                float mA, mB; f2unpack(mm, mA, mB);
                u64 epk = f2pack(ex2f(mA), ex2f(mB));
                u64 w2 = f2mul(q5.x, epk);        // op * exp2(mm)
                wacc = f2add(wacc, w2);
                ssacc = f2fma(w2, f2relu(res), ssacc);
            }
        }
    }

    float wA, wB, sA, sB2;
    f2unpack(wacc, wA, wB);
    f2unpack(ssacc, sA, sB2);
    if (v0) {
        g_partial[(split*2 + 0)*N_PTS + s0] = wA;
        g_partial[(split*2 + 1)*N_PTS + s0] = sA;
    }
    if (v1) {
        g_partial[(split*2 + 0)*N_PTS + s1] = wB;
        g_partial[(split*2 + 1)*N_PTS + s1] = sB2;
    }
}

// ---------------------------------------------------------------------------
// Deterministic fixed-order reduction over splits + un-permute.
// ---------------------------------------------------------------------------
__global__ void reduce_kernel(float* __restrict__ out) {
    int slot = blockIdx.x * blockDim.x + threadIdx.x;
    if (slot >= N_PTS) return;
    float a = 0.f, b = 0.f;
#pragma unroll
    for (int s = 0; s < NSPLIT; ++s) {
        a += g_partial[(s*2 + 0) * N_PTS + slot];
        b += g_partial[(s*2 + 1) * N_PTS + slot];
    }
    int o = g_perm[slot];
    out[o] = a;
    out[N_PTS + o] = b;
}

extern "C" void kernel_launch(void* const* d_in, const int* in_sizes, int n_in,
                              void* d_out, int out_size) {
    const float* pts      = (const float*)d_in[0];  // network_pts
    // d_in[1] network_view, d_in[2] network_tx: unused by the reference math
    const float* xyz      = (const float*)d_in[3];
    const float* sh_dc    = (const float*)d_in[4];
    const float* sh_rest  = (const float*)d_in[5];
    const float* scaling  = (const float*)d_in[6];
    const float* rotation = (const float*)d_in[7];
    const float* opacity  = (const float*)d_in[8];

    zero_kernel<<<NCELL/256, 256>>>();
    cell_count<<<N_PTS/256, 256>>>(pts);
    scan_kernel<<<1, 1024>>>();
    scatter_kernel<<<N_PTS/256, 256>>>(pts);
    worklist_kernel<<<1, 1024>>>();
    prep_kernel<<<(N_GAUSS + 255)/256, 256>>>(xyz, sh_dc, sh_rest, scaling, rotation, opacity);
    mask_kernel<<<NCELL*32/256, 256>>>();
    main_kernel<<<MAXITEMS, 128>>>();
    reduce_kernel<<<(N_PTS + 255)/256, 256>>>((float*)d_out);
}

// round 6
// speedup vs baseline: 1.4915x; 1.4915x over previous
#include <cuda_runtime.h>

#define N_GAUSS 4096
#define N_PTS 32768
#define NSPLIT 8
#define NBLK 128                 /* gaussian blocks of 32 */
#define BPS (NBLK / NSPLIT)      /* 16 blocks per split */
#define U2G 14                   /* ulonglong2 per gaussian (28 dup float2 slots) */
#define NCELL 4096               /* 16^3 grid, cell side 0.5 over [-4,4] */
#define NGRP 512                 /* groups of 64 sorted points (one warp each) */

typedef unsigned long long u64;

__device__ ulonglong2 g_prm2[N_GAUSS * U2G];
__device__ float4 g_ginfo[N_GAUSS];            // center xyz, T
__device__ float  g_partial[NSPLIT * 2 * N_PTS];
__device__ int    g_cnt[NCELL];
__device__ int    g_cur[NCELL];
__device__ int    g_cid[N_PTS];
__device__ int    g_perm[N_PTS];
__device__ float4 g_spts[N_PTS];
__device__ unsigned g_gmask[NGRP * NBLK];

__device__ __forceinline__ float ex2f(float x) {
    float y; asm("ex2.approx.ftz.f32 %0, %1;" : "=f"(y) : "f"(x)); return y;
}
__device__ __forceinline__ float rsqf(float x) {
    float y; asm("rsqrt.approx.ftz.f32 %0, %1;" : "=f"(y) : "f"(x)); return y;
}
__device__ __forceinline__ u64 f2fma(u64 a, u64 b, u64 c) {
    u64 d; asm("fma.rn.f32x2 %0, %1, %2, %3;" : "=l"(d) : "l"(a), "l"(b), "l"(c)); return d;
}
__device__ __forceinline__ u64 f2mul(u64 a, u64 b) {
    u64 d; asm("mul.rn.f32x2 %0, %1, %2;" : "=l"(d) : "l"(a), "l"(b)); return d;
}
__device__ __forceinline__ u64 f2add(u64 a, u64 b) {
    u64 d; asm("add.rn.f32x2 %0, %1, %2;" : "=l"(d) : "l"(a), "l"(b)); return d;
}
__device__ __forceinline__ u64 f2pack(float lo, float hi) {
    u64 d; asm("mov.b64 %0, {%1, %2};" : "=l"(d) : "f"(lo), "f"(hi)); return d;
}
__device__ __forceinline__ void f2unpack(u64 v, float& lo, float& hi) {
    asm("mov.b64 {%0, %1}, %2;" : "=f"(lo), "=f"(hi) : "l"(v));
}
__device__ __forceinline__ u64 f2relu(u64 v) {
    unsigned lo = (unsigned)v, hi = (unsigned)(v >> 32);
    lo &= ~(unsigned)(((int)lo) >> 31);
    hi &= ~(unsigned)(((int)hi) >> 31);
    return ((u64)hi << 32) | lo;
}

// ---------------------------------------------------------------------------
// Spatial binning of points (cell = 0.5, 16^3 over [-4,4], borders clamped).
// Within-cell order from atomics is nondeterministic but provably harmless:
// it only changes which exact-+0.0 terms enter each point's sum (bitwise
// no-ops) and which lane computes which point (identical arithmetic).
// ---------------------------------------------------------------------------
__global__ void zero_kernel() {
    int i = blockIdx.x * blockDim.x + threadIdx.x;
    if (i < NCELL) g_cnt[i] = 0;
}

__global__ void cell_count(const float* __restrict__ pts) {
    int i = blockIdx.x * blockDim.x + threadIdx.x;
    if (i >= N_PTS) return;
    float x = pts[i*3+0], y = pts[i*3+1], z = pts[i*3+2];
    int ix = min(15, max(0, (int)floorf((x + 4.f) * 2.f)));
    int iy = min(15, max(0, (int)floorf((y + 4.f) * 2.f)));
    int iz = min(15, max(0, (int)floorf((z + 4.f) * 2.f)));
    int c = ix | (iy << 4) | (iz << 8);
    g_cid[i] = c;
    atomicAdd(&g_cnt[c], 1);
}

__global__ void __launch_bounds__(1024) scan_kernel() {
    __shared__ int ps[1024];
    int t = threadIdx.x;
    int l0 = g_cnt[t*4+0], l1 = g_cnt[t*4+1], l2 = g_cnt[t*4+2], l3 = g_cnt[t*4+3];
    int s = l0 + l1 + l2 + l3;
    ps[t] = s; __syncthreads();
    for (int off = 1; off < 1024; off <<= 1) {
        int v = (t >= off) ? ps[t - off] : 0;
        __syncthreads();
        ps[t] += v;
        __syncthreads();
    }
    int run = ps[t] - s;
    g_cur[t*4+0] = run; run += l0;
    g_cur[t*4+1] = run; run += l1;
    g_cur[t*4+2] = run; run += l2;
    g_cur[t*4+3] = run;
}

__global__ void scatter_kernel(const float* __restrict__ pts) {
    int i = blockIdx.x * blockDim.x + threadIdx.x;
    if (i >= N_PTS) return;
    int slot = atomicAdd(&g_cur[g_cid[i]], 1);
    g_perm[slot] = i;
    // store NEGATED coords (main kernel computes e = g + (-p))
    g_spts[slot] = make_float4(-pts[i*3+0], -pts[i*3+1], -pts[i*3+2], 0.f);
}

// ---------------------------------------------------------------------------
// Per-gaussian preprocessing (dup layout) + ginfo for mask build.
//  slots: 0:gx 1:gy 2:gz 3:T 4..9:P0..P5 10:op 11:c0 12..27:c1..c15
// T = 230*smax^2: n2 >= T  =>  exp(-0.5*maha) == +0.0f exactly, in the
// reference too -> lossless cull.
// ---------------------------------------------------------------------------
__global__ void prep_kernel(const float* __restrict__ xyz,
                            const float* __restrict__ sh_dc,
                            const float* __restrict__ sh_rest,
                            const float* __restrict__ scaling,
                            const float* __restrict__ rotation,
                            const float* __restrict__ opacity) {
    int g = blockIdx.x * blockDim.x + threadIdx.x;
    if (g >= N_GAUSS) return;

    float qr = rotation[g*4+0], qx = rotation[g*4+1];
    float qy = rotation[g*4+2], qz = rotation[g*4+3];
    float qn = rsqrtf(qr*qr + qx*qx + qy*qy + qz*qz);
    qr *= qn; qx *= qn; qy *= qn; qz *= qn;

    float R00 = 1.f - 2.f*(qy*qy + qz*qz), R01 = 2.f*(qx*qy - qr*qz), R02 = 2.f*(qx*qz + qr*qy);
    float R10 = 2.f*(qx*qy + qr*qz), R11 = 1.f - 2.f*(qx*qx + qz*qz), R12 = 2.f*(qy*qz - qr*qx);
    float R20 = 2.f*(qx*qz - qr*qy), R21 = 2.f*(qy*qz + qr*qx), R22 = 1.f - 2.f*(qx*qx + qy*qy);

    float s0 = expf(scaling[g*3+0]);
    float s1 = expf(scaling[g*3+1]);
    float s2 = expf(scaling[g*3+2]);
    float iv0 = 1.f/(s0*s0), iv1 = 1.f/(s1*s1), iv2 = 1.f/(s2*s2);
    float smax = fmaxf(s0, fmaxf(s1, s2));
    float T = 230.f * smax * smax;

    float Pxx = iv0*R00*R00 + iv1*R01*R01 + iv2*R02*R02;
    float Pyy = iv0*R10*R10 + iv1*R11*R11 + iv2*R12*R12;
    float Pzz = iv0*R20*R20 + iv1*R21*R21 + iv2*R22*R22;
    float Pxy = iv0*R00*R10 + iv1*R01*R11 + iv2*R02*R12;
    float Pxz = iv0*R00*R20 + iv1*R01*R21 + iv2*R02*R22;
    float Pyz = iv0*R10*R20 + iv1*R11*R21 + iv2*R12*R22;

    const float kk = -0.7213475204444817f;  // -0.5 * log2(e)
    float op = 1.f / (1.f + expf(-opacity[g]));

    const float C0 = 0.28209479177387814f;
    const float C1 = 0.4886025119029199f;
    const float* sr = sh_rest + g*15;
    float c[16];
    c[0]  =  C0 * sh_dc[g];
    c[1]  = -C1 * sr[0];
    c[2]  =  C1 * sr[1];
    c[3]  = -C1 * sr[2];
    c[4]  =  1.0925484305920792f  * sr[3];
    c[5]  = -1.0925484305920792f  * sr[4];
    c[6]  =  0.31539156525252005f * sr[5];
    c[7]  = -1.0925484305920792f  * sr[6];
    c[8]  =  0.5462742152960396f  * sr[7];
    c[9]  = -0.5900435899266435f  * sr[8];
    c[10] =  2.890611442640554f   * sr[9];
    c[11] = -0.4570457994644658f  * sr[10];
    c[12] =  0.3731763325901154f  * sr[11];
    c[13] = -0.4570457994644658f  * sr[12];
    c[14] =  1.445305721320277f   * sr[13];
    c[15] = -0.5900435899266435f  * sr[14];

    float gx = xyz[g*3+0], gy = xyz[g*3+1], gz = xyz[g*3+2];
    g_ginfo[g] = make_float4(gx, gy, gz, T);

    float v[28];
    v[0] = gx; v[1] = gy; v[2] = gz; v[3] = T;
    v[4] = kk*Pxx; v[5] = kk*Pyy; v[6] = kk*Pzz;
    v[7] = 2.f*kk*Pxy; v[8] = 2.f*kk*Pxz; v[9] = 2.f*kk*Pyz;
    v[10] = op; v[11] = c[0];
#pragma unroll
    for (int i = 0; i < 15; ++i) v[12+i] = c[1+i];
    v[27] = 0.f;

    float2* o = (float2*)&g_prm2[g * U2G];
#pragma unroll
    for (int i = 0; i < 28; ++i) o[i] = make_float2(v[i], v[i]);
}

// ---------------------------------------------------------------------------
// Group masks: one warp per group of 64 sorted points. Warp computes the
// exact AABB of its (negated) points, then tests all 4096 gaussians:
// bit set iff dist(AABB, -gaussian_center)^2 < T. Deterministic given the
// permutation; permutation differences only toggle exact-zero terms.
// ---------------------------------------------------------------------------
__global__ void __launch_bounds__(256) gmask_kernel() {
    int grp  = (blockIdx.x * 256 + threadIdx.x) >> 5;
    int lane = threadIdx.x & 31;
    if (grp >= NGRP) return;

    float4 a = g_spts[grp*64 + 2*lane];
    float4 b = g_spts[grp*64 + 2*lane + 1];
    float mnx = fminf(a.x, b.x), mxx = fmaxf(a.x, b.x);
    float mny = fminf(a.y, b.y), mxy = fmaxf(a.y, b.y);
    float mnz = fminf(a.z, b.z), mxz = fmaxf(a.z, b.z);
#pragma unroll
    for (int o = 16; o; o >>= 1) {
        mnx = fminf(mnx, __shfl_xor_sync(0xFFFFFFFFu, mnx, o));
        mxx = fmaxf(mxx, __shfl_xor_sync(0xFFFFFFFFu, mxx, o));
        mny = fminf(mny, __shfl_xor_sync(0xFFFFFFFFu, mny, o));
        mxy = fmaxf(mxy, __shfl_xor_sync(0xFFFFFFFFu, mxy, o));
        mnz = fminf(mnz, __shfl_xor_sync(0xFFFFFFFFu, mnz, o));
        mxz = fmaxf(mxz, __shfl_xor_sync(0xFFFFFFFFu, mxz, o));
    }

    for (int blk = 0; blk < NBLK; ++blk) {
        float4 gi = g_ginfo[blk*32 + lane];
        float gx = -gi.x, gy = -gi.y, gz = -gi.z;   // compare in negated space
        float dx = gx - fminf(fmaxf(gx, mnx), mxx);
        float dy = gy - fminf(fmaxf(gy, mny), mxy);
        float dz = gz - fminf(fmaxf(gz, mnz), mxz);
        float d2 = dx*dx + dy*dy + dz*dz;
        unsigned m = __ballot_sync(0xFFFFFFFFu, d2 < gi.w);
        if (lane == 0) g_gmask[grp*NBLK + blk] = m;
    }
}

// ---------------------------------------------------------------------------
// Main kernel: warp = one group (64 points, 2/lane, all lanes full).
// blockIdx.y = gaussian-block split (16 blocks each). Warp walks only set
// mask bits; per-point ballot is the second-level cull. Params via broadcast
// LDG (hot subset is L1-resident).
// ---------------------------------------------------------------------------
__global__ void __launch_bounds__(128) main_kernel() {
    int warp = threadIdx.x >> 5;
    int lane = threadIdx.x & 31;
    int grp  = blockIdx.x * 4 + warp;
    int split = blockIdx.y;

    int s0 = grp*64 + 2*lane;
    int s1 = s0 + 1;
    float4 pa = g_spts[s0], pb = g_spts[s1];
    u64 npx = f2pack(pa.x, pb.x);
    u64 npy = f2pack(pa.y, pb.y);
    u64 npz = f2pack(pa.z, pb.z);

    const u64 K3  = 0x4040000040400000ULL;  // { 3, 3}
    const u64 K5  = 0x40A0000040A00000ULL;  // { 5, 5}
    const u64 Kn2 = 0xC0000000C0000000ULL;  // {-2,-2}
    const u64 Kn3 = 0xC0400000C0400000ULL;  // {-3,-3}
    const u64 SGN = 0x8000000080000000ULL;

    u64 wacc = 0, ssacc = 0;
    const unsigned* mrow = &g_gmask[grp * NBLK + split * BPS];

#pragma unroll 1
    for (int bi = 0; bi < BPS; ++bi) {
        unsigned m = mrow[bi];
        int gbase = (split * BPS + bi) * 32;
        while (m) {
            int j = __ffs(m) - 1;
            m &= m - 1;
            const ulonglong2* G = &g_prm2[(gbase + j) * U2G];
            ulonglong2 q0 = G[0], q1 = G[1];

            u64 ex = f2add(q0.x, npx);   // e = gauss - point
            u64 ey = f2add(q0.y, npy);
            u64 ez = f2add(q1.x, npz);
            u64 exx = f2mul(ex, ex), eyy = f2mul(ey, ey), ezz = f2mul(ez, ez);
            u64 n2 = f2add(f2add(exx, eyy), ezz);

            float nA, nB; f2unpack(n2, nA, nB);
            float Tv, Tv2; f2unpack(q1.y, Tv, Tv2);
            bool act = (nA < Tv) || (nB < Tv);
            if (__ballot_sync(0xFFFFFFFFu, act)) {
                ulonglong2 q2 = G[2], q3 = G[3], q4 = G[4];
                u64 pxy = f2mul(ex, ey), pxz = f2mul(ex, ez), pyz = f2mul(ey, ez);

                // exponent (pre-scaled by -0.5*log2e)
                u64 mm = f2mul(exx, q2.x);
                mm = f2fma(eyy, q2.y, mm);
                mm = f2fma(ezz, q3.x, mm);
                mm = f2fma(pxy, q3.y, mm);
                mm = f2fma(pxz, q4.x, mm);
                mm = f2fma(pyz, q4.y, mm);

                // aux polynomials in e
                u64 n2n  = n2 ^ SGN;
                u64 eyyn = eyy ^ SGN;
                u64 t6  = f2fma(K3, ezz, n2n);    // 3ezz - n2
                u64 uq  = f2add(exx, eyyn);       // exx - eyy
                u64 t9  = f2fma(K3, exx, eyyn);   // 3exx - eyy
                u64 w5  = f2fma(K5, ezz, n2n);    // 5ezz - n2
                u64 t12 = f2fma(Kn2, n2, w5);     // 5ezz - 3n2
                u64 t15 = f2fma(Kn3, ezz, uq);    // exx - eyy - 3ezz

                ulonglong2 q5 = G[5], q6 = G[6], q7 = G[7];
                u64 S1 = f2fma(ex, q7.x, f2fma(ez, q6.y, f2mul(ey, q6.x)));
                ulonglong2 q8 = G[8], q9 = G[9];
                u64 S2 = f2fma(uq, q9.y,
                         f2fma(pxz, q9.x,
                         f2fma(t6, q8.y,
                         f2fma(pyz, q8.x, f2mul(pxy, q7.y)))));
                ulonglong2 q10 = G[10], q11 = G[11], q12 = G[12], q13 = G[13];
                u64 m9  = f2mul(ey, t9);
                u64 m11 = f2mul(ey, w5);
                u64 m13 = f2mul(ex, w5);
                u64 m15 = f2mul(ex, t15);
                u64 S3a = f2mul(m9, q10.x);
                S3a = f2fma(m11, q11.x, S3a);
                S3a = f2fma(m13, q12.x, S3a);
                S3a = f2fma(m15, q13.x, S3a);
                u64 m10 = f2mul(pxy, ez);
                u64 m12 = f2mul(ez, t12);
                u64 m14 = f2mul(ez, uq);
                u64 S3b = f2mul(m10, q10.y);
                S3b = f2fma(m12, q11.y, S3b);
                S3b = f2fma(m14, q12.y, S3b);
                u64 S3 = f2add(S3a, S3b);

                // Horner in rinv: res = c0 + r*(S1 + r*(S2 + r*S3))
                u64 rq = f2pack(rsqf(nA), rsqf(nB));
                u64 res = f2fma(rq, S3, S2);
                res = f2fma(rq, res, S1);
                res = f2fma(rq, res, q5.y);

                float mA, mB; f2unpack(mm, mA, mB);
                u64 epk = f2pack(ex2f(mA), ex2f(mB));
                u64 w2 = f2mul(q5.x, epk);        // op * exp2(mm)
                wacc = f2add(wacc, w2);
                ssacc = f2fma(w2, f2relu(res), ssacc);
            }
        }
    }

    float wA, wB, sA, sB2;
    f2unpack(wacc, wA, wB);
    f2unpack(ssacc, sA, sB2);
    g_partial[(split*2 + 0)*N_PTS + s0] = wA;
    g_partial[(split*2 + 0)*N_PTS + s1] = wB;
    g_partial[(split*2 + 1)*N_PTS + s0] = sA;
    g_partial[(split*2 + 1)*N_PTS + s1] = sB2;
}

// ---------------------------------------------------------------------------
// Deterministic fixed-order reduction over splits + un-permute.
// ---------------------------------------------------------------------------
__global__ void reduce_kernel(float* __restrict__ out) {
    int slot = blockIdx.x * blockDim.x + threadIdx.x;
    if (slot >= N_PTS) return;
    float a = 0.f, b = 0.f;
#pragma unroll
    for (int s = 0; s < NSPLIT; ++s) {
        a += g_partial[(s*2 + 0) * N_PTS + slot];
        b += g_partial[(s*2 + 1) * N_PTS + slot];
    }
    int o = g_perm[slot];
    out[o] = a;
    out[N_PTS + o] = b;
}

extern "C" void kernel_launch(void* const* d_in, const int* in_sizes, int n_in,
                              void* d_out, int out_size) {
    const float* pts      = (const float*)d_in[0];  // network_pts
    // d_in[1] network_view, d_in[2] network_tx: unused by the reference math
    const float* xyz      = (const float*)d_in[3];
    const float* sh_dc    = (const float*)d_in[4];
    const float* sh_rest  = (const float*)d_in[5];
    const float* scaling  = (const float*)d_in[6];
    const float* rotation = (const float*)d_in[7];
    const float* opacity  = (const float*)d_in[8];

    zero_kernel<<<NCELL/256, 256>>>();
    cell_count<<<N_PTS/256, 256>>>(pts);
    scan_kernel<<<1, 1024>>>();
    scatter_kernel<<<N_PTS/256, 256>>>(pts);
    prep_kernel<<<(N_GAUSS + 255)/256, 256>>>(xyz, sh_dc, sh_rest, scaling, rotation, opacity);
    gmask_kernel<<<NGRP*32/256, 256>>>();
    main_kernel<<<dim3(NGRP/4, NSPLIT), 128>>>();
    reduce_kernel<<<(N_PTS + 255)/256, 256>>>((float*)d_out);
}

// round 7
// speedup vs baseline: 1.6591x; 1.1124x over previous
#include <cuda_runtime.h>

#define N_GAUSS 4096
#define N_PTS 32768
#define NSPLIT 8
#define NBLK 128                 /* gaussian blocks of 32 */
#define BPS (NBLK / NSPLIT)      /* 16 blocks per split */
#define U2G 14                   /* ulonglong2 per gaussian (28 dup float2 slots) */
#define NCELL 4096               /* 16^3 grid, cell side 0.5 over [-4,4] */
#define NGRP 512                 /* groups of 64 sorted points (one warp each) */

typedef unsigned long long u64;

__device__ ulonglong2 g_prm2[N_GAUSS * U2G];
__device__ float4 g_ginfo[N_GAUSS];            // center xyz, T
__device__ float  g_partial[NSPLIT * 2 * N_PTS];
__device__ int    g_cnt[NCELL];
__device__ int    g_cur[NCELL];
__device__ int    g_cid[N_PTS];
__device__ int    g_perm[N_PTS];
__device__ float4 g_spts[N_PTS];

__device__ __forceinline__ float ex2f(float x) {
    float y; asm("ex2.approx.ftz.f32 %0, %1;" : "=f"(y) : "f"(x)); return y;
}
__device__ __forceinline__ float rsqf(float x) {
    float y; asm("rsqrt.approx.ftz.f32 %0, %1;" : "=f"(y) : "f"(x)); return y;
}
__device__ __forceinline__ u64 f2fma(u64 a, u64 b, u64 c) {
    u64 d; asm("fma.rn.f32x2 %0, %1, %2, %3;" : "=l"(d) : "l"(a), "l"(b), "l"(c)); return d;
}
__device__ __forceinline__ u64 f2mul(u64 a, u64 b) {
    u64 d; asm("mul.rn.f32x2 %0, %1, %2;" : "=l"(d) : "l"(a), "l"(b)); return d;
}
__device__ __forceinline__ u64 f2add(u64 a, u64 b) {
    u64 d; asm("add.rn.f32x2 %0, %1, %2;" : "=l"(d) : "l"(a), "l"(b)); return d;
}
__device__ __forceinline__ u64 f2pack(float lo, float hi) {
    u64 d; asm("mov.b64 %0, {%1, %2};" : "=l"(d) : "f"(lo), "f"(hi)); return d;
}
__device__ __forceinline__ void f2unpack(u64 v, float& lo, float& hi) {
    asm("mov.b64 {%0, %1}, %2;" : "=f"(lo), "=f"(hi) : "l"(v));
}
__device__ __forceinline__ u64 f2relu(u64 v) {
    unsigned lo = (unsigned)v, hi = (unsigned)(v >> 32);
    lo &= ~(unsigned)(((int)lo) >> 31);
    hi &= ~(unsigned)(((int)hi) >> 31);
    return ((u64)hi << 32) | lo;
}

// ---------------------------------------------------------------------------
// Spatial binning by MORTON cell code (cell = 0.5, 16^3 over [-4,4], borders
// clamped). Z-order makes consecutive sorted points spatially compact, so a
// 64-point group's AABB is ~1.0^3 instead of a 4-long slab.
// Within-cell order from atomics is nondeterministic but provably harmless:
// group masks are supersets of every member point's nonzero reach, excluded
// terms are exactly +0.0, accumulators are never -0.0, and in-set evaluation
// order is fixed ascending -> output bits are permutation-invariant.
// ---------------------------------------------------------------------------
__global__ void cell_count(const float* __restrict__ pts) {
    int i = blockIdx.x * blockDim.x + threadIdx.x;
    if (i >= N_PTS) return;
    float x = pts[i*3+0], y = pts[i*3+1], z = pts[i*3+2];
    int ix = min(15, max(0, (int)floorf((x + 4.f) * 2.f)));
    int iy = min(15, max(0, (int)floorf((y + 4.f) * 2.f)));
    int iz = min(15, max(0, (int)floorf((z + 4.f) * 2.f)));
    int c = 0;
#pragma unroll
    for (int b = 0; b < 4; ++b)
        c |= (((ix >> b) & 1) << (3*b)) | (((iy >> b) & 1) << (3*b + 1))
           | (((iz >> b) & 1) << (3*b + 2));
    g_cid[i] = c;
    atomicAdd(&g_cnt[c], 1);
}

__global__ void __launch_bounds__(1024) scan_kernel() {
    __shared__ int ps[1024];
    int t = threadIdx.x;
    int l0 = g_cnt[t*4+0], l1 = g_cnt[t*4+1], l2 = g_cnt[t*4+2], l3 = g_cnt[t*4+3];
    int s = l0 + l1 + l2 + l3;
    ps[t] = s; __syncthreads();
    for (int off = 1; off < 1024; off <<= 1) {
        int v = (t >= off) ? ps[t - off] : 0;
        __syncthreads();
        ps[t] += v;
        __syncthreads();
    }
    int run = ps[t] - s;
    g_cur[t*4+0] = run; run += l0;
    g_cur[t*4+1] = run; run += l1;
    g_cur[t*4+2] = run; run += l2;
    g_cur[t*4+3] = run;
}

__global__ void scatter_kernel(const float* __restrict__ pts) {
    int i = blockIdx.x * blockDim.x + threadIdx.x;
    if (i >= N_PTS) return;
    int slot = atomicAdd(&g_cur[g_cid[i]], 1);
    g_perm[slot] = i;
    // store NEGATED coords (main kernel computes e = g + (-p))
    g_spts[slot] = make_float4(-pts[i*3+0], -pts[i*3+1], -pts[i*3+2], 0.f);
}

// ---------------------------------------------------------------------------
// Per-gaussian preprocessing (dup layout) + ginfo + zeroing of g_cnt.
//  slots: 0:gx 1:gy 2:gz 3:T 4..9:P0..P5 10:op 11:c0 12..27:c1..c15
// T = 230*smax^2: n2 >= T  =>  exp(-0.5*maha) == +0.0f exactly (also in the
// reference) -> lossless cull.
// ---------------------------------------------------------------------------
__global__ void prep_kernel(const float* __restrict__ xyz,
                            const float* __restrict__ sh_dc,
                            const float* __restrict__ sh_rest,
                            const float* __restrict__ scaling,
                            const float* __restrict__ rotation,
                            const float* __restrict__ opacity) {
    int g = blockIdx.x * blockDim.x + threadIdx.x;
    if (g >= N_GAUSS) return;
    g_cnt[g] = 0;   // N_GAUSS == NCELL: fold the zeroing launch in here

    float qr = rotation[g*4+0], qx = rotation[g*4+1];
    float qy = rotation[g*4+2], qz = rotation[g*4+3];
    float qn = rsqrtf(qr*qr + qx*qx + qy*qy + qz*qz);
    qr *= qn; qx *= qn; qy *= qn; qz *= qn;

    float R00 = 1.f - 2.f*(qy*qy + qz*qz), R01 = 2.f*(qx*qy - qr*qz), R02 = 2.f*(qx*qz + qr*qy);
    float R10 = 2.f*(qx*qy + qr*qz), R11 = 1.f - 2.f*(qx*qx + qz*qz), R12 = 2.f*(qy*qz - qr*qx);
    float R20 = 2.f*(qx*qz - qr*qy), R21 = 2.f*(qy*qz + qr*qx), R22 = 1.f - 2.f*(qx*qx + qy*qy);

    float s0 = expf(scaling[g*3+0]);
    float s1 = expf(scaling[g*3+1]);
    float s2 = expf(scaling[g*3+2]);
    float iv0 = 1.f/(s0*s0), iv1 = 1.f/(s1*s1), iv2 = 1.f/(s2*s2);
    float smax = fmaxf(s0, fmaxf(s1, s2));
    float T = 230.f * smax * smax;

    float Pxx = iv0*R00*R00 + iv1*R01*R01 + iv2*R02*R02;
    float Pyy = iv0*R10*R10 + iv1*R11*R11 + iv2*R12*R12;
    float Pzz = iv0*R20*R20 + iv1*R21*R21 + iv2*R22*R22;
    float Pxy = iv0*R00*R10 + iv1*R01*R11 + iv2*R02*R12;
    float Pxz = iv0*R00*R20 + iv1*R01*R21 + iv2*R02*R22;
    float Pyz = iv0*R10*R20 + iv1*R11*R21 + iv2*R12*R22;

    const float kk = -0.7213475204444817f;  // -0.5 * log2(e)
    float op = 1.f / (1.f + expf(-opacity[g]));

    const float C0 = 0.28209479177387814f;
    const float C1 = 0.4886025119029199f;
    const float* sr = sh_rest + g*15;
    float c[16];
    c[0]  =  C0 * sh_dc[g];
    c[1]  = -C1 * sr[0];
    c[2]  =  C1 * sr[1];
    c[3]  = -C1 * sr[2];
    c[4]  =  1.0925484305920792f  * sr[3];
    c[5]  = -1.0925484305920792f  * sr[4];
    c[6]  =  0.31539156525252005f * sr[5];
    c[7]  = -1.0925484305920792f  * sr[6];
    c[8]  =  0.5462742152960396f  * sr[7];
    c[9]  = -0.5900435899266435f  * sr[8];
    c[10] =  2.890611442640554f   * sr[9];
    c[11] = -0.4570457994644658f  * sr[10];
    c[12] =  0.3731763325901154f  * sr[11];
    c[13] = -0.4570457994644658f  * sr[12];
    c[14] =  1.445305721320277f   * sr[13];
    c[15] = -0.5900435899266435f  * sr[14];

    float gx = xyz[g*3+0], gy = xyz[g*3+1], gz = xyz[g*3+2];
    // negated center for AABB tests in negated-point space
    g_ginfo[g] = make_float4(-gx, -gy, -gz, T);

    float v[28];
    v[0] = gx; v[1] = gy; v[2] = gz; v[3] = T;
    v[4] = kk*Pxx; v[5] = kk*Pyy; v[6] = kk*Pzz;
    v[7] = 2.f*kk*Pxy; v[8] = 2.f*kk*Pxz; v[9] = 2.f*kk*Pyz;
    v[10] = op; v[11] = c[0];
#pragma unroll
    for (int i = 0; i < 15; ++i) v[12+i] = c[1+i];
    v[27] = 0.f;

    float2* o = (float2*)&g_prm2[g * U2G];
#pragma unroll
    for (int i = 0; i < 28; ++i) o[i] = make_float2(v[i], v[i]);
}

// ---------------------------------------------------------------------------
// Main kernel: warp = one group (64 Morton-adjacent points, 2/lane).
// blockIdx.y = gaussian-block split (16 blocks each). The warp computes its
// own point AABB, builds each 32-gaussian block mask inline (box-dist < sqrtT
// via ballot), then walks set bits with a per-point ballot as second cull.
// ---------------------------------------------------------------------------
__global__ void __launch_bounds__(128) main_kernel() {
    int warp = threadIdx.x >> 5;
    int lane = threadIdx.x & 31;
    int grp  = blockIdx.x * 4 + warp;
    int split = blockIdx.y;

    int s0 = grp*64 + 2*lane;
    int s1 = s0 + 1;
    float4 pa = g_spts[s0], pb = g_spts[s1];
    u64 npx = f2pack(pa.x, pb.x);
    u64 npy = f2pack(pa.y, pb.y);
    u64 npz = f2pack(pa.z, pb.z);

    // warp AABB of the (negated) points
    float mnx = fminf(pa.x, pb.x), mxx = fmaxf(pa.x, pb.x);
    float mny = fminf(pa.y, pb.y), mxy = fmaxf(pa.y, pb.y);
    float mnz = fminf(pa.z, pb.z), mxz = fmaxf(pa.z, pb.z);
#pragma unroll
    for (int o = 16; o; o >>= 1) {
        mnx = fminf(mnx, __shfl_xor_sync(0xFFFFFFFFu, mnx, o));
        mxx = fmaxf(mxx, __shfl_xor_sync(0xFFFFFFFFu, mxx, o));
        mny = fminf(mny, __shfl_xor_sync(0xFFFFFFFFu, mny, o));
        mxy = fmaxf(mxy, __shfl_xor_sync(0xFFFFFFFFu, mxy, o));
        mnz = fminf(mnz, __shfl_xor_sync(0xFFFFFFFFu, mnz, o));
        mxz = fmaxf(mxz, __shfl_xor_sync(0xFFFFFFFFu, mxz, o));
    }

    const u64 K3  = 0x4040000040400000ULL;  // { 3, 3}
    const u64 K5  = 0x40A0000040A00000ULL;  // { 5, 5}
    const u64 Kn2 = 0xC0000000C0000000ULL;  // {-2,-2}
    const u64 Kn3 = 0xC0400000C0400000ULL;  // {-3,-3}
    const u64 SGN = 0x8000000080000000ULL;

    u64 wacc = 0, ssacc = 0;

#pragma unroll 1
    for (int bi = 0; bi < BPS; ++bi) {
        int gbase = (split * BPS + bi) * 32;

        // inline block mask: gaussian reaches the AABB?
        float4 gi = g_ginfo[gbase + lane];   // negated center, T
        float dx = gi.x - fminf(fmaxf(gi.x, mnx), mxx);
        float dy = gi.y - fminf(fmaxf(gi.y, mny), mxy);
        float dz = gi.z - fminf(fmaxf(gi.z, mnz), mxz);
        float d2 = fmaf(dx, dx, fmaf(dy, dy, dz*dz));
        unsigned m = __ballot_sync(0xFFFFFFFFu, d2 < gi.w);

        while (m) {
            int j = __ffs(m) - 1;
            m &= m - 1;
            const ulonglong2* G = &g_prm2[(gbase + j) * U2G];
            ulonglong2 q0 = G[0], q1 = G[1];

            u64 ex = f2add(q0.x, npx);   // e = gauss - point
            u64 ey = f2add(q0.y, npy);
            u64 ez = f2add(q1.x, npz);
            u64 exx = f2mul(ex, ex), eyy = f2mul(ey, ey), ezz = f2mul(ez, ez);
            u64 n2 = f2add(f2add(exx, eyy), ezz);

            float nA, nB; f2unpack(n2, nA, nB);
            float Tv, Tv2; f2unpack(q1.y, Tv, Tv2);
            bool act = (nA < Tv) || (nB < Tv);
            if (__ballot_sync(0xFFFFFFFFu, act)) {
                ulonglong2 q2 = G[2], q3 = G[3], q4 = G[4];
                u64 pxy = f2mul(ex, ey), pxz = f2mul(ex, ez), pyz = f2mul(ey, ez);

                // exponent (pre-scaled by -0.5*log2e)
                u64 mm = f2mul(exx, q2.x);
                mm = f2fma(eyy, q2.y, mm);
                mm = f2fma(ezz, q3.x, mm);
                mm = f2fma(pxy, q3.y, mm);
                mm = f2fma(pxz, q4.x, mm);
                mm = f2fma(pyz, q4.y, mm);

                // aux polynomials in e
                u64 n2n  = n2 ^ SGN;
                u64 eyyn = eyy ^ SGN;
                u64 t6  = f2fma(K3, ezz, n2n);    // 3ezz - n2
                u64 uq  = f2add(exx, eyyn);       // exx - eyy
                u64 t9  = f2fma(K3, exx, eyyn);   // 3exx - eyy
                u64 w5  = f2fma(K5, ezz, n2n);    // 5ezz - n2
                u64 t12 = f2fma(Kn2, n2, w5);     // 5ezz - 3n2
                u64 t15 = f2fma(Kn3, ezz, uq);    // exx - eyy - 3ezz

                ulonglong2 q5 = G[5], q6 = G[6], q7 = G[7];
                u64 S1 = f2fma(ex, q7.x, f2fma(ez, q6.y, f2mul(ey, q6.x)));
                ulonglong2 q8 = G[8], q9 = G[9];
                u64 S2 = f2fma(uq, q9.y,
                         f2fma(pxz, q9.x,
                         f2fma(t6, q8.y,
                         f2fma(pyz, q8.x, f2mul(pxy, q7.y)))));
                ulonglong2 q10 = G[10], q11 = G[11], q12 = G[12], q13 = G[13];
                u64 m9  = f2mul(ey, t9);
                u64 m11 = f2mul(ey, w5);
                u64 m13 = f2mul(ex, w5);
                u64 m15 = f2mul(ex, t15);
                u64 S3a = f2mul(m9, q10.x);
                S3a = f2fma(m11, q11.x, S3a);
                S3a = f2fma(m13, q12.x, S3a);
                S3a = f2fma(m15, q13.x, S3a);
                u64 m10 = f2mul(pxy, ez);
                u64 m12 = f2mul(ez, t12);
                u64 m14 = f2mul(ez, uq);
                u64 S3b = f2mul(m10, q10.y);
                S3b = f2fma(m12, q11.y, S3b);
                S3b = f2fma(m14, q12.y, S3b);
                u64 S3 = f2add(S3a, S3b);

                // Horner in rinv: res = c0 + r*(S1 + r*(S2 + r*S3))
                u64 rq = f2pack(rsqf(nA), rsqf(nB));
                u64 res = f2fma(rq, S3, S2);
                res = f2fma(rq, res, S1);
                res = f2fma(rq, res, q5.y);

                float mA, mB; f2unpack(mm, mA, mB);
                u64 epk = f2pack(ex2f(mA), ex2f(mB));
                u64 w2 = f2mul(q5.x, epk);        // op * exp2(mm)
                wacc = f2add(wacc, w2);
                ssacc = f2fma(w2, f2relu(res), ssacc);
            }
        }
    }

    float wA, wB, sA, sB2;
    f2unpack(wacc, wA, wB);
    f2unpack(ssacc, sA, sB2);
    g_partial[(split*2 + 0)*N_PTS + s0] = wA;
    g_partial[(split*2 + 0)*N_PTS + s1] = wB;
    g_partial[(split*2 + 1)*N_PTS + s0] = sA;
    g_partial[(split*2 + 1)*N_PTS + s1] = sB2;
}

// ---------------------------------------------------------------------------
// Deterministic fixed-order reduction over splits + un-permute.
// ---------------------------------------------------------------------------
__global__ void reduce_kernel(float* __restrict__ out) {
    int slot = blockIdx.x * blockDim.x + threadIdx.x;
    if (slot >= N_PTS) return;
    float a = 0.f, b = 0.f;
#pragma unroll
    for (int s = 0; s < NSPLIT; ++s) {
        a += g_partial[(s*2 + 0) * N_PTS + slot];
        b += g_partial[(s*2 + 1) * N_PTS + slot];
    }
    int o = g_perm[slot];
    out[o] = a;
    out[N_PTS + o] = b;
}

extern "C" void kernel_launch(void* const* d_in, const int* in_sizes, int n_in,
                              void* d_out, int out_size) {
    const float* pts      = (const float*)d_in[0];  // network_pts
    // d_in[1] network_view, d_in[2] network_tx: unused by the reference math
    const float* xyz      = (const float*)d_in[3];
    const float* sh_dc    = (const float*)d_in[4];
    const float* sh_rest  = (const float*)d_in[5];
    const float* scaling  = (const float*)d_in[6];
    const float* rotation = (const float*)d_in[7];
    const float* opacity  = (const float*)d_in[8];

    prep_kernel<<<(N_GAUSS + 255)/256, 256>>>(xyz, sh_dc, sh_rest, scaling, rotation, opacity);
    cell_count<<<N_PTS/256, 256>>>(pts);
    scan_kernel<<<1, 1024>>>();
    scatter_kernel<<<N_PTS/256, 256>>>(pts);
    main_kernel<<<dim3(NGRP/4, NSPLIT), 128>>>();
    reduce_kernel<<<(N_PTS + 255)/256, 256>>>((float*)d_out);
}